// round 5
// baseline (speedup 1.0000x reference)
#include <cuda_runtime.h>
#include <cuda_bf16.h>
#include <math.h>

#define D_MODEL 1024
#define NH 16
#define HD 64
#define BATCH 2
#define SEQ 2048
#define MROWS (BATCH*SEQ)

// Scratch: q,k,v in [B,H,S,HD], ctx in [B*S, D_MODEL]
__device__ float g_q[BATCH*NH*SEQ*HD];
__device__ float g_k[BATCH*NH*SEQ*HD];
__device__ float g_v[BATCH*NH*SEQ*HD];
__device__ float g_ctx[MROWS*D_MODEL];

__device__ __forceinline__ unsigned f2tf(float x) {
    unsigned r;
    asm("cvt.rna.tf32.f32 %0, %1;" : "=r"(r) : "f"(x));
    return r;
}

__device__ __forceinline__ void mma8(float* c, uint4 a, uint2 b) {
    asm volatile(
        "mma.sync.aligned.m16n8k8.row.col.f32.tf32.tf32.f32 "
        "{%0,%1,%2,%3}, {%4,%5,%6,%7}, {%8,%9}, {%0,%1,%2,%3};"
        : "+f"(c[0]), "+f"(c[1]), "+f"(c[2]), "+f"(c[3])
        : "r"(a.x), "r"(a.y), "r"(a.z), "r"(a.w), "r"(b.x), "r"(b.y));
}

// Fragment-native smem layouts (tf32 words):
// A-layout (16-row m-blocks x 8-col k-blocks): block = (kb*NMB + mb), 512B each;
//   within: lane = (r%8)*4 + (k%4) -> lane*16; reg = (r%16)/8 + 2*((k%8)/4) -> +reg*4.
//   Read: one LDS.128 per (mb,kb) per warp -> a-frag {a0,a1,a2,a3} in order.
// B-layout (8-col n-blocks x 8-row k-blocks): block = (kb*NNB + nb), 256B each;
//   within: lane = (n%8)*4 + (k%4) -> lane*8; reg = (k%8)/4 -> +reg*4.
//   Read: one LDS.64 per (nb,kb) per warp -> b-frag {b0,b1}.

// ============================================================================
// TF32 GEMM, fused over z: Y = X @ W^T. 4 warps (2x2), warp tile 64x64.
// Tile 128x128, K chunks of 32. Register-prefetch double buffer.
// ============================================================================
#define TBM 128
#define TBN 128
#define TBK 32
#define A_BYTES (TBM*TBK*4)      // 16384, frag A-layout (NMB=8, NKB=4)
#define B_BYTES (TBN*TBK*4)      // 16384, frag B-layout (NNB=16)
#define STG (A_BYTES + B_BYTES)
#define GSMEM (2*STG)            // 65536

__global__ __launch_bounds__(128) void gemm_tf32(
    const float* __restrict__ X,
    const float* __restrict__ W0, const float* __restrict__ W1, const float* __restrict__ W2,
    float* __restrict__ Y0, float* __restrict__ Y1, float* __restrict__ Y2,
    int proj_mode)
{
    extern __shared__ char gsm[];
    const int tid = threadIdx.x;
    const int wid = tid >> 5, lane = tid & 31;
    const int g = lane >> 2, tq = lane & 3;
    const int wm = wid & 1, wn = wid >> 1;      // 2 x 2 warp grid
    const int bm = blockIdx.y * TBM, bn = blockIdx.x * TBN;
    const int z = blockIdx.z;
    const float* W = (z == 0) ? W0 : (z == 1) ? W1 : W2;
    float* Y = (z == 0) ? Y0 : (z == 1) ? Y1 : Y2;

    float acc[4][8][4];
    #pragma unroll
    for (int i = 0; i < 4; i++)
        #pragma unroll
        for (int j = 0; j < 8; j++)
            #pragma unroll
            for (int r = 0; r < 4; r++) acc[i][j][r] = 0.f;

    float4 pa[8], pb[8];
    auto ldregs = [&](int kt) {
        #pragma unroll
        for (int i = 0; i < 8; i++) {
            int c = tid + i * 128, r = c >> 3, k4 = (c & 7) << 2;
            pa[i] = *(const float4*)(X + (size_t)(bm + r) * D_MODEL + kt + k4);
            pb[i] = *(const float4*)(W + (size_t)(bn + r) * D_MODEL + kt + k4);
        }
    };
    auto stg = [&](int buf) {
        char* Ab = gsm + buf * STG;
        char* Bb = Ab + A_BYTES;
        #pragma unroll
        for (int i = 0; i < 8; i++) {
            int c = tid + i * 128, r = c >> 3, k4 = (c & 7) << 2;
            // A: base = (kb*8 + mb)*512 + (r%8)*64 + rowbit*4 + colhalf*8 ; +j*16
            unsigned ab = (unsigned)(((k4 >> 3) * 8 + (r >> 4)) * 512
                        + (r & 7) * 64 + ((r >> 3) & 1) * 4 + ((k4 >> 2) & 1) * 8);
            *(unsigned*)(Ab + ab +  0) = f2tf(pa[i].x);
            *(unsigned*)(Ab + ab + 16) = f2tf(pa[i].y);
            *(unsigned*)(Ab + ab + 32) = f2tf(pa[i].z);
            *(unsigned*)(Ab + ab + 48) = f2tf(pa[i].w);
            // B: base = (kb*16 + nb)*256 + (r%8)*32 + colhalf*4 ; +j*8
            unsigned bb = (unsigned)(((k4 >> 3) * 16 + (r >> 3)) * 256
                        + (r & 7) * 32 + ((k4 >> 2) & 1) * 4);
            *(unsigned*)(Bb + bb +  0) = f2tf(pb[i].x);
            *(unsigned*)(Bb + bb +  8) = f2tf(pb[i].y);
            *(unsigned*)(Bb + bb + 16) = f2tf(pb[i].z);
            *(unsigned*)(Bb + bb + 24) = f2tf(pb[i].w);
        }
    };

    ldregs(0);
    const int NCH = D_MODEL / TBK;   // 32
    for (int j = 0; j < NCH; j++) {
        const int buf = j & 1;
        stg(buf);
        __syncthreads();
        if (j + 1 < NCH) ldregs((j + 1) * TBK);

        const char* Ab = gsm + buf * STG;
        const char* Bb = Ab + A_BYTES;
        #pragma unroll
        for (int kk8 = 0; kk8 < 4; kk8++) {
            uint4 a[4];
            #pragma unroll
            for (int mt = 0; mt < 4; mt++)
                a[mt] = *(const uint4*)(Ab + ((kk8 * 8 + wm * 4 + mt) << 9) + lane * 16);
            uint2 b[8];
            #pragma unroll
            for (int nt = 0; nt < 8; nt++)
                b[nt] = *(const uint2*)(Bb + ((kk8 * 16 + wn * 8 + nt) << 8) + lane * 8);
            #pragma unroll
            for (int mt = 0; mt < 4; mt++)
                #pragma unroll
                for (int nt = 0; nt < 8; nt++)
                    mma8(acc[mt][nt], a[mt], b[nt]);
        }
        __syncthreads();
    }

    // epilogue
    #pragma unroll
    for (int mt = 0; mt < 4; mt++) {
        #pragma unroll
        for (int nt = 0; nt < 8; nt++) {
            int row0 = bm + wm * 64 + mt * 16 + g;
            int col = bn + wn * 64 + nt * 8 + tq * 2;
            #pragma unroll
            for (int half = 0; half < 2; half++) {
                int row = row0 + half * 8;
                float v0 = acc[mt][nt][half * 2 + 0];
                float v1 = acc[mt][nt][half * 2 + 1];
                if (proj_mode) {
                    int b2 = row >> 11, s2 = row & (SEQ - 1);
                    int hh = col >> 6, d0 = col & 63;
                    float* dst = Y + ((size_t)((b2 * NH + hh) * SEQ + s2)) * HD + d0;
                    dst[0] = v0; dst[1] = v1;
                } else {
                    float* dst = Y + (size_t)row * D_MODEL + col;
                    dst[0] = v0; dst[1] = v1;
                }
            }
        }
    }
}

// ============================================================================
// Causal flash attention: TF32 mma.sync, 128-row Q tiles, 8 warps, 64-row KV
// tiles. Q/P in frag A-layout, K/V in frag B-layout -> LDS.128/LDS.64 frags.
// ============================================================================
#define QT 128
#define KT 64
#define SQ_OFF 0                        // Q: 128x64 A-layout, 32KB
#define SK_OFF 32768                    // K: 64x64 B-layout, 16KB
#define SV_OFF 49152                    // V: 64x64 B-layout (n=d,k=kv), 16KB
#define SP_OFF 65536                    // P: 128x64 A-layout, 32KB
#define FSMEM 98304

__global__ __launch_bounds__(256, 2) void flash_kernel()
{
    extern __shared__ char smf[];
    char* Qb = smf + SQ_OFF;
    char* Kb = smf + SK_OFF;
    char* Vb = smf + SV_OFF;
    char* Pb = smf + SP_OFF;

    const int tid = threadIdx.x;
    const int w = tid >> 5, lane = tid & 31;
    const int g = lane >> 2, tq = lane & 3;
    const int bh = blockIdx.y;
    const int b = bh / NH, h = bh % NH;
    const int qt = (gridDim.x - 1 - blockIdx.x);   // heavy blocks first
    const int q0 = qt * QT;

    const float* qbase = g_q + (size_t)(b * NH + h) * SEQ * HD;
    const float* kbase = g_k + (size_t)(b * NH + h) * SEQ * HD;
    const float* vbase = g_v + (size_t)(b * NH + h) * SEQ * HD;

    // load Q tile (128x64) into A-layout, pre-scaled by 1/sqrt(HD)
    #pragma unroll
    for (int i = 0; i < 8; i++) {
        int c = tid + i * 256, r = c >> 4, c4 = (c & 15) << 2;
        float4 vq = *(const float4*)(qbase + (size_t)(q0 + r) * HD + c4);
        unsigned qb = (unsigned)(((c4 >> 3) * 8 + (r >> 4)) * 512
                    + (r & 7) * 64 + ((r >> 3) & 1) * 4 + ((c4 >> 2) & 1) * 8);
        *(unsigned*)(Qb + qb +  0) = f2tf(vq.x * 0.125f);
        *(unsigned*)(Qb + qb + 16) = f2tf(vq.y * 0.125f);
        *(unsigned*)(Qb + qb + 32) = f2tf(vq.z * 0.125f);
        *(unsigned*)(Qb + qb + 48) = f2tf(vq.w * 0.125f);
    }

    float o[8][4];
    #pragma unroll
    for (int nt = 0; nt < 8; nt++)
        #pragma unroll
        for (int r = 0; r < 4; r++) o[nt][r] = 0.f;
    float m0 = -INFINITY, m1 = -INFINITY, l0 = 0.f, l1 = 0.f;

    const int prow = w * 16 + g;
    const int row0g = q0 + prow;
    const int row1g = row0g + 8;

    // P store bases (A-layout): col = nt*8 + 2tq + {0,1}
    const unsigned pt0 = (unsigned)(w * 512 + g * 64
                       + ((2 * tq) & 3) * 16 + (((2 * tq) >> 2) & 1) * 8);
    const unsigned pt1 = (unsigned)(w * 512 + g * 64
                       + ((2 * tq + 1) & 3) * 16 + (((2 * tq + 1) >> 2) & 1) * 8);

    const int ktiles = 2 * qt + 2;
    for (int kt = 0; kt < ktiles; kt++) {
        const int kv0 = kt * KT;
        // load K, V tiles (64x64 each) into frag B-layouts
        #pragma unroll
        for (int i = 0; i < 4; i++) {
            int c = tid + i * 256, r = c >> 4, c4 = (c & 15) << 2;
            float4 vk = *(const float4*)(kbase + (size_t)(kv0 + r) * HD + c4);
            // K element (n=r, k=c4+j): base + j*8
            unsigned kb = (unsigned)(((c4 >> 3) * 8 + (r >> 3)) * 256
                        + (r & 7) * 32 + ((c4 >> 2) & 1) * 4);
            *(unsigned*)(Kb + kb +  0) = f2tf(vk.x);
            *(unsigned*)(Kb + kb +  8) = f2tf(vk.y);
            *(unsigned*)(Kb + kb + 16) = f2tf(vk.z);
            *(unsigned*)(Kb + kb + 24) = f2tf(vk.w);
            float4 vv = *(const float4*)(vbase + (size_t)(kv0 + r) * HD + c4);
            // V element (n=c4+j, k=r): lane=(c%8)*4+(r%4), reg=(r%8)/4 -> +j*32
            unsigned vb = (unsigned)(((r >> 3) * 8 + (c4 >> 3)) * 256
                        + ((c4 & 7) * 4 + (r & 3)) * 8 + ((r >> 2) & 1) * 4);
            *(unsigned*)(Vb + vb +  0) = f2tf(vv.x);
            *(unsigned*)(Vb + vb + 32) = f2tf(vv.y);
            *(unsigned*)(Vb + vb + 64) = f2tf(vv.z);
            *(unsigned*)(Vb + vb + 96) = f2tf(vv.w);
        }
        __syncthreads();

        // scores S = Q K^T (16 rows x 64 cols per warp)
        float sc[8][4];
        #pragma unroll
        for (int nt = 0; nt < 8; nt++)
            #pragma unroll
            for (int r = 0; r < 4; r++) sc[nt][r] = 0.f;
        #pragma unroll
        for (int kk8 = 0; kk8 < 8; kk8++) {
            uint4 a = *(const uint4*)(Qb + ((kk8 * 8 + w) << 9) + lane * 16);
            #pragma unroll
            for (int nt = 0; nt < 8; nt++) {
                uint2 bb = *(const uint2*)(Kb + ((kk8 * 8 + nt) << 8) + lane * 8);
                mma8(sc[nt], a, bb);
            }
        }

        // causal mask
        const bool msk0 = (kv0 + KT - 1 > row0g);
        const bool msk1 = (kv0 + KT - 1 > row1g);
        if (msk0 | msk1) {
            #pragma unroll
            for (int nt = 0; nt < 8; nt++) {
                int c0 = kv0 + nt * 8 + tq * 2;
                if (msk0) {
                    if (c0     > row0g) sc[nt][0] = -1e30f;
                    if (c0 + 1 > row0g) sc[nt][1] = -1e30f;
                }
                if (msk1) {
                    if (c0     > row1g) sc[nt][2] = -1e30f;
                    if (c0 + 1 > row1g) sc[nt][3] = -1e30f;
                }
            }
        }

        // online softmax
        float rm0 = -1e30f, rm1 = -1e30f;
        #pragma unroll
        for (int nt = 0; nt < 8; nt++) {
            rm0 = fmaxf(rm0, fmaxf(sc[nt][0], sc[nt][1]));
            rm1 = fmaxf(rm1, fmaxf(sc[nt][2], sc[nt][3]));
        }
        rm0 = fmaxf(rm0, __shfl_xor_sync(0xffffffffu, rm0, 1));
        rm0 = fmaxf(rm0, __shfl_xor_sync(0xffffffffu, rm0, 2));
        rm1 = fmaxf(rm1, __shfl_xor_sync(0xffffffffu, rm1, 1));
        rm1 = fmaxf(rm1, __shfl_xor_sync(0xffffffffu, rm1, 2));

        float nm0 = fmaxf(m0, rm0), nm1 = fmaxf(m1, rm1);
        float a0 = __expf(m0 - nm0), a1 = __expf(m1 - nm1);
        m0 = nm0; m1 = nm1;

        float rs0 = 0.f, rs1 = 0.f;
        #pragma unroll
        for (int nt = 0; nt < 8; nt++) {
            float p0 = __expf(sc[nt][0] - nm0); sc[nt][0] = p0; rs0 += p0;
            float p1 = __expf(sc[nt][1] - nm0); sc[nt][1] = p1; rs0 += p1;
            float p2 = __expf(sc[nt][2] - nm1); sc[nt][2] = p2; rs1 += p2;
            float p3 = __expf(sc[nt][3] - nm1); sc[nt][3] = p3; rs1 += p3;
        }
        rs0 += __shfl_xor_sync(0xffffffffu, rs0, 1);
        rs0 += __shfl_xor_sync(0xffffffffu, rs0, 2);
        rs1 += __shfl_xor_sync(0xffffffffu, rs1, 1);
        rs1 += __shfl_xor_sync(0xffffffffu, rs1, 2);
        l0 = l0 * a0 + rs0;
        l1 = l1 * a1 + rs1;

        #pragma unroll
        for (int nt = 0; nt < 8; nt++) {
            o[nt][0] *= a0; o[nt][1] *= a0;
            o[nt][2] *= a1; o[nt][3] *= a1;
        }

        // write P into A-layout (warp-private rows; rowbit(+8) -> +4 bytes)
        #pragma unroll
        for (int nt = 0; nt < 8; nt++) {
            unsigned a0o = (unsigned)(nt * 4096) + pt0;
            unsigned a1o = (unsigned)(nt * 4096) + pt1;
            *(unsigned*)(Pb + a0o)     = f2tf(sc[nt][0]);
            *(unsigned*)(Pb + a1o)     = f2tf(sc[nt][1]);
            *(unsigned*)(Pb + a0o + 4) = f2tf(sc[nt][2]);
            *(unsigned*)(Pb + a1o + 4) = f2tf(sc[nt][3]);
        }
        __syncwarp();

        // O += P V
        #pragma unroll
        for (int kk8 = 0; kk8 < 8; kk8++) {
            uint4 a = *(const uint4*)(Pb + ((kk8 * 8 + w) << 9) + lane * 16);
            #pragma unroll
            for (int nt = 0; nt < 8; nt++) {
                uint2 bb = *(const uint2*)(Vb + ((kk8 * 8 + nt) << 8) + lane * 8);
                mma8(o[nt], a, bb);
            }
        }
        __syncthreads();   // protect Kb/Vb before next iteration's stores
    }

    // epilogue: normalize, write ctx[b*S + row][h*64 + d]
    float inv0 = 1.f / l0, inv1 = 1.f / l1;
    #pragma unroll
    for (int nt = 0; nt < 8; nt++) {
        int colg = h * HD + nt * 8 + tq * 2;
        size_t r0 = (size_t)(b * SEQ + row0g) * D_MODEL + colg;
        size_t r1 = (size_t)(b * SEQ + row1g) * D_MODEL + colg;
        g_ctx[r0]     = o[nt][0] * inv0;
        g_ctx[r0 + 1] = o[nt][1] * inv0;
        g_ctx[r1]     = o[nt][2] * inv1;
        g_ctx[r1 + 1] = o[nt][3] * inv1;
    }
}

// ============================================================================
extern "C" void kernel_launch(void* const* d_in, const int* in_sizes, int n_in,
                              void* d_out, int out_size)
{
    const float* x  = (const float*)d_in[0];
    const float* qW = (const float*)d_in[1];
    const float* kW = (const float*)d_in[2];
    const float* vW = (const float*)d_in[3];
    const float* oW = (const float*)d_in[4];
    float* out = (float*)d_out;

    float *pq, *pk, *pv, *pctx;
    cudaGetSymbolAddress((void**)&pq, g_q);
    cudaGetSymbolAddress((void**)&pk, g_k);
    cudaGetSymbolAddress((void**)&pv, g_v);
    cudaGetSymbolAddress((void**)&pctx, g_ctx);

    cudaFuncSetAttribute(gemm_tf32, cudaFuncAttributeMaxDynamicSharedMemorySize, GSMEM);
    cudaFuncSetAttribute(flash_kernel, cudaFuncAttributeMaxDynamicSharedMemorySize, FSMEM);

    // Fused QKV projection: one launch, z = {q,k,v}
    dim3 ggridQKV(D_MODEL / TBN, MROWS / TBM, 3);   // (8, 32, 3) = 768 CTAs
    gemm_tf32<<<ggridQKV, 128, GSMEM>>>(x, qW, kW, vW, pq, pk, pv, 1);

    flash_kernel<<<dim3(SEQ / QT, BATCH * NH), 256, FSMEM>>>();

    dim3 ggridO(D_MODEL / TBN, MROWS / TBM, 1);     // (8, 32) = 256 CTAs
    gemm_tf32<<<ggridO, 128, GSMEM>>>(pctx, oW, oW, oW, out, out, out, 0);
}